// round 5
// baseline (speedup 1.0000x reference)
#include <cuda_runtime.h>

// Problem constants: C=16, B=64, G=2048, S=8, L=4, infer_step=3.
#define NC 16
#define NB 64
#define NG 2048
#define NS 8
#define NL 4
#define NSTEPS 3
#define GAMMA 0.001f
#define KINV  1442.6950408889634f   /* 1000 * log2(e) */
#define GLN2  6.931471805599453e-4f /* gamma * ln(2)  */
#define BG (NB*NG)            // 131072 = 2^17
#define TOT (NC*NB*NG)        // 2097152

// Fixed-point log-domain encoding: zbits = float_bits(v*KF11 + 1.5*2^23).
// Low mantissa bits == round(v*KINV*2^11); monotone in v; diffs are exact.
#define KF11  2954639.5f            /* KINV * 2048 */
#define MAGF  12582912.0f           /* 1.5 * 2^23 */
#define MAGI  0x4B400000            /* bits of MAGF */
#define LIM   258048                /* 126 << 11 */
#define EB_LIT 1065056216           /* (127<<23) - 297000  (minimax bias, +-3.5%) */
#define EB_ONE 1065353216           /* (127<<23): exact 1.0 at diff==0 */

// Scratch (no cudaMalloc allowed).
__device__ float d_rbuf[TOT];
__device__ float d_ubuf[2][TOT];
__device__ int4  d_itr[NC * (NG/32) * NS * 32];   // transposed indices, 4MB
__device__ unsigned d_mC[NSTEPS * NC];
__device__ unsigned d_mG[NSTEPS];

__device__ __forceinline__ float ex2f(float x) { float y; asm("ex2.approx.f32 %0, %1;" : "=f"(y) : "f"(x)); return y; }
__device__ __forceinline__ float lg2f(float x) { float y; asm("lg2.approx.f32 %0, %1;" : "=f"(y) : "f"(x)); return y; }
__device__ __forceinline__ float rcpf(float x) { float y; asm("rcp.approx.f32 %0, %1;" : "=f"(y) : "f"(x)); return y; }

// Order-preserving float<->uint encoding so atomicMax works for any sign.
__device__ __forceinline__ unsigned fenc(float f) {
    unsigned u = __float_as_uint(f);
    return (u & 0x80000000u) ? ~u : (u | 0x80000000u);
}
__device__ __forceinline__ float fdec(unsigned u) {
    return __uint_as_float((u & 0x80000000u) ? (u ^ 0x80000000u) : ~u);
}

__global__ void init_max_kernel() {
    int t = threadIdx.x;
    if (t < NSTEPS * NC) d_mC[t] = 0u;
    if (t < NSTEPS)      d_mG[t] = 0u;
}

// One-time transpose of I for coalesced hot-loop index loads:
// d_itr flat = ((c*64 + g/32)*8 + s)*32 + (g%32)  <-  I[(c, g, s)] as int4.
__global__ __launch_bounds__(256) void transpose_I_kernel(const int* __restrict__ I) {
    const int t  = blockIdx.x * 256 + threadIdx.x;
    const int gl = t & 31;
    const int s  = (t >> 5) & 7;
    const int gb = (t >> 8) & 63;
    const int c  = t >> 14;
    const int4* __restrict__ in = reinterpret_cast<const int4*>(I);
    d_itr[t] = in[((size_t)(c * NG + gb * 32 + gl)) * NS + s];
}

// Int-domain softand + streaming softor update (exp2 via exponent injection on
// the ALU pipe; only rcp touches MUFU). Mr MUST be initialized to 0 (not a large
// negative) -- encoded values are ~1.26e9 and Mr-Mn must not underflow int32.
#define ROW_UPD_I(vA, vB, vC, vD, Mr, Sr)                                          \
    {                                                                              \
        int m_  = min(min(vA, vB), min(vC, vD));                                   \
        int Mn  = max(Mr, m_);                                                     \
        float e0 = __int_as_float(min(max(Mn - (vA), -LIM), LIM) * 4096 + EB_LIT); \
        float e1 = __int_as_float(min(max(Mn - (vB), -LIM), LIM) * 4096 + EB_LIT); \
        float e2 = __int_as_float(min(max(Mn - (vC), -LIM), LIM) * 4096 + EB_LIT); \
        float e3 = __int_as_float(min(max(Mn - (vD), -LIM), LIM) * 4096 + EB_LIT); \
        float d_ = (e0 + e1) + (e2 + e3);                                          \
        float t_ = rcpf(d_);                                                       \
        float f_ = __int_as_float(max(Mr - Mn, -LIM) * 4096 + EB_ONE);             \
        Sr = fmaf(Sr, f_, t_);                                                     \
        Mr = Mn;                                                                   \
    }

// Kernel A: r_raw[c,b,g] = softor_S( softand_L( gather ) ), plus per-clause max.
// Rows live in shared as int4 log-domain encodings; one LDS.128 serves 4 rows.
__global__ __launch_bounds__(256, 4) void clause_kernel(const float* __restrict__ x,
                                                        int step) {
    __shared__ int4 rows4[NG];   // 32 KB
    __shared__ float wmax[8];

    const int c  = blockIdx.z;
    const int b0 = blockIdx.y * 4;
    const int g0 = blockIdx.x * (NG / 4);
    const int tid = threadIdx.x;

    if (step == 0) {
        const float* __restrict__ xp = x + (size_t)b0 * NG;
        for (int i = tid; i < NG; i += 256) {
            int4 z;
            z.x = __float_as_int(fmaf(xp[i],          KF11, MAGF));
            z.y = __float_as_int(fmaf(xp[NG + i],     KF11, MAGF));
            z.z = __float_as_int(fmaf(xp[2 * NG + i], KF11, MAGF));
            z.w = __float_as_int(fmaf(xp[3 * NG + i], KF11, MAGF));
            rows4[i] = z;
        }
    } else {
        const float mg = fdec(d_mG[step - 1]);
        const float scK = ((mg > 1.0f) ? (1.0f / mg) : 1.0f) * KF11;
        const float* __restrict__ up = d_ubuf[(step - 1) & 1] + (size_t)(c * NB + b0) * NG;
        for (int i = tid; i < NG; i += 256) {
            int4 z;
            z.x = __float_as_int(fmaf(up[i],          scK, MAGF));
            z.y = __float_as_int(fmaf(up[NG + i],     scK, MAGF));
            z.z = __float_as_int(fmaf(up[2 * NG + i], scK, MAGF));
            z.w = __float_as_int(fmaf(up[3 * NG + i], scK, MAGF));
            rows4[i] = z;
        }
    }
    __syncthreads();

    float lmax = -1e30f;

    #pragma unroll
    for (int gg = 0; gg < 2; gg++) {
        const int g = g0 + gg * 256 + tid;
        const int lane = g & 31;
        const int4* __restrict__ ip = d_itr + ((size_t)(c * (NG/32) + (g >> 5)) * NS) * 32;

        // Init running max to 0: encoded values are all >= MAGI > 0, and this
        // keeps Mr - Mn within int32 range on the first substitution.
        int M0 = 0, M1 = 0, M2 = 0, M3 = 0;
        float S0 = 0.0f, S1 = 0.0f, S2 = 0.0f, S3 = 0.0f;

        int4 nxt = ip[lane];                       // s = 0, coalesced
        #pragma unroll
        for (int s = 0; s < NS; s++) {
            const int4 q = nxt;
            if (s < NS - 1) nxt = ip[(s + 1) * 32 + lane];
            const int4 A  = rows4[q.x];
            const int4 Bv = rows4[q.y];
            const int4 Cv = rows4[q.z];
            const int4 Dv = rows4[q.w];
            ROW_UPD_I(A.x, Bv.x, Cv.x, Dv.x, M0, S0);
            ROW_UPD_I(A.y, Bv.y, Cv.y, Dv.y, M1, S1);
            ROW_UPD_I(A.z, Bv.z, Cv.z, Dv.z, M2, S2);
            ROW_UPD_I(A.w, Bv.w, Cv.w, Dv.w, M3, S3);
        }

        // Decode running max back to value-domain: A = (Mr - MAGI)/KF11.
        const float r0 = fmaf(GLN2, lg2f(S0), (float)(M0 - MAGI) * (1.0f / KF11));
        const float r1 = fmaf(GLN2, lg2f(S1), (float)(M1 - MAGI) * (1.0f / KF11));
        const float r2 = fmaf(GLN2, lg2f(S2), (float)(M2 - MAGI) * (1.0f / KF11));
        const float r3 = fmaf(GLN2, lg2f(S3), (float)(M3 - MAGI) * (1.0f / KF11));

        float* __restrict__ rb = d_rbuf + (size_t)(c * NB + b0) * NG + g;
        rb[0]      = r0;
        rb[NG]     = r1;
        rb[2 * NG] = r2;
        rb[3 * NG] = r3;
        lmax = fmaxf(fmaxf(fmaxf(lmax, r0), fmaxf(r1, r2)), r3);
    }

    #pragma unroll
    for (int o = 16; o > 0; o >>= 1) lmax = fmaxf(lmax, __shfl_xor_sync(0xffffffffu, lmax, o));
    if ((tid & 31) == 0) wmax[tid >> 5] = lmax;
    __syncthreads();
    if (tid == 0) {
        float m2 = wmax[0];
        #pragma unroll
        for (int w = 1; w < 8; w++) m2 = fmaxf(m2, wmax[w]);
        atomicMax(&d_mC[step * NC + c], fenc(m2));
    }
}

// Kernel B: finalize r' with per-clause max, combine u = softor2(R, r'), track
// global max. float4-vectorized (latency-bound kernel: raise MLP, cut LSU ops).
__global__ __launch_bounds__(256) void combine_kernel(const float* __restrict__ x, int step) {
    __shared__ float wmax[8];
    const int tid = threadIdx.x;
    const int base = blockIdx.x * 2048;          // 2048-aligned => clause constant per block
    const int c = base >> 17;

    const float mc = fdec(d_mC[step * NC + c]);
    const float scC = (mc > 1.0f) ? (1.0f / mc) : 1.0f;

    float scP = 1.0f;
    if (step > 0) {
        const float mg = fdec(d_mG[step - 1]);
        if (mg > 1.0f) scP = 1.0f / mg;
    }

    const float4* __restrict__ rp = reinterpret_cast<const float4*>(d_rbuf + base);
    const float4* __restrict__ ap = (step == 0)
        ? reinterpret_cast<const float4*>(x + (base & (BG - 1)))
        : reinterpret_cast<const float4*>(d_ubuf[(step - 1) & 1] + base);
    float4* __restrict__ uo = reinterpret_cast<float4*>(d_ubuf[step & 1] + base);

    float lmax = -1e30f;
    #pragma unroll
    for (int k = 0; k < 2; k++) {
        const int i = k * 256 + tid;             // float4 index within block chunk
        const float4 rv = rp[i];
        const float4 av = ap[i];
        float4 u;
        {
            const float r = rv.x * scC, a = av.x * scP;
            const float M = fmaxf(a, r);
            u.x = fmaf(GLN2, lg2f(1.0f + ex2f(-fabsf(a - r) * KINV)), M);
        }
        {
            const float r = rv.y * scC, a = av.y * scP;
            const float M = fmaxf(a, r);
            u.y = fmaf(GLN2, lg2f(1.0f + ex2f(-fabsf(a - r) * KINV)), M);
        }
        {
            const float r = rv.z * scC, a = av.z * scP;
            const float M = fmaxf(a, r);
            u.z = fmaf(GLN2, lg2f(1.0f + ex2f(-fabsf(a - r) * KINV)), M);
        }
        {
            const float r = rv.w * scC, a = av.w * scP;
            const float M = fmaxf(a, r);
            u.w = fmaf(GLN2, lg2f(1.0f + ex2f(-fabsf(a - r) * KINV)), M);
        }
        uo[i] = u;
        lmax = fmaxf(fmaxf(fmaxf(lmax, u.x), fmaxf(u.y, u.z)), u.w);
    }

    #pragma unroll
    for (int o = 16; o > 0; o >>= 1) lmax = fmaxf(lmax, __shfl_xor_sync(0xffffffffu, lmax, o));
    if ((tid & 31) == 0) wmax[tid >> 5] = lmax;
    __syncthreads();
    if (tid == 0) {
        float m2 = wmax[0];
        #pragma unroll
        for (int w = 1; w < 8; w++) m2 = fmaxf(m2, wmax[w]);
        atomicMax(&d_mG[step], fenc(m2));
    }
}

__global__ __launch_bounds__(256) void final_kernel(float* __restrict__ out) {
    const int i = blockIdx.x * 256 + threadIdx.x;
    const float mg = fdec(d_mG[NSTEPS - 1]);
    const float sc = (mg > 1.0f) ? (1.0f / mg) : 1.0f;
    out[i] = d_ubuf[(NSTEPS - 1) & 1][i] * sc;
}

extern "C" void kernel_launch(void* const* d_in, const int* in_sizes, int n_in,
                              void* d_out, int out_size) {
    const float* x = (const float*)d_in[0];   // (B, G) float32
    const int*   I = (const int*)d_in[1];     // (C, G, S, L) int32

    init_max_kernel<<<1, 64>>>();
    transpose_I_kernel<<<(NC * NG * NS) / 256, 256>>>(I);

    dim3 gridA(4, NB / 4, NC);                // (g-quarter, b-group, clause)
    for (int t = 0; t < NSTEPS; t++) {
        clause_kernel<<<gridA, 256>>>(x, t);
        combine_kernel<<<TOT / 2048, 256>>>(x, t);
    }
    final_kernel<<<TOT / 256, 256>>>((float*)d_out);
}

// round 6
// speedup vs baseline: 1.4869x; 1.4869x over previous
#include <cuda_runtime.h>

// Problem constants: C=16, B=64, G=2048, S=8, L=4, infer_step=3.
#define NC 16
#define NB 64
#define NG 2048
#define NS 8
#define NL 4
#define NSTEPS 3
#define GAMMA 0.001f
#define KINV  1442.6950408889634f   /* 1000 * log2(e) */
#define GLN2  6.931471805599453e-4f /* gamma * ln(2)  */
#define BG (NB*NG)            // 131072 = 2^17
#define TOT (NC*NB*NG)        // 2097152

// Fixed-point log-domain encoding: zbits = float_bits(v*KF11 + 1.5*2^23).
// Low mantissa bits == round(v*KINV*2^11); monotone in v; diffs are exact.
#define KF11  2954639.5f            /* KINV * 2048 */
#define MAGF  12582912.0f           /* 1.5 * 2^23 */
#define MAGI  0x4B400000            /* bits of MAGF */
#define LIM   258048                /* 126 << 11 */
#define EB_LIT 1065056216           /* (127<<23) - 297000  (minimax bias, +-3.5%) */
#define EB_ONE 1065353216           /* (127<<23): exact 1.0 at diff==0 */

// Scratch (no cudaMalloc allowed).
__device__ float d_rbuf[TOT];
__device__ float d_ubuf[2][TOT];
__device__ int4  d_itr[NC * (NG/32) * NS * 32];   // transposed indices, 4MB
__device__ unsigned d_mC[NSTEPS * NC];
__device__ unsigned d_mG[NSTEPS];

__device__ __forceinline__ float ex2f(float x) { float y; asm("ex2.approx.f32 %0, %1;" : "=f"(y) : "f"(x)); return y; }
__device__ __forceinline__ float lg2f(float x) { float y; asm("lg2.approx.f32 %0, %1;" : "=f"(y) : "f"(x)); return y; }
__device__ __forceinline__ float rcpf(float x) { float y; asm("rcp.approx.f32 %0, %1;" : "=f"(y) : "f"(x)); return y; }

// Order-preserving float<->uint encoding so atomicMax works for any sign.
__device__ __forceinline__ unsigned fenc(float f) {
    unsigned u = __float_as_uint(f);
    return (u & 0x80000000u) ? ~u : (u | 0x80000000u);
}
__device__ __forceinline__ float fdec(unsigned u) {
    return __uint_as_float((u & 0x80000000u) ? (u ^ 0x80000000u) : ~u);
}

__global__ void init_max_kernel() {
    int t = threadIdx.x;
    if (t < NSTEPS * NC) d_mC[t] = 0u;
    if (t < NSTEPS)      d_mG[t] = 0u;
}

// One-time transpose of I for coalesced hot-loop index loads:
// d_itr flat = ((c*64 + g/32)*8 + s)*32 + (g%32)  <-  I[(c, g, s)] as int4.
__global__ __launch_bounds__(256) void transpose_I_kernel(const int* __restrict__ I) {
    const int t  = blockIdx.x * 256 + threadIdx.x;
    const int gl = t & 31;
    const int s  = (t >> 5) & 7;
    const int gb = (t >> 8) & 63;
    const int c  = t >> 14;
    const int4* __restrict__ in = reinterpret_cast<const int4*>(I);
    d_itr[t] = in[((size_t)(c * NG + gb * 32 + gl)) * NS + s];
}

// Int-domain softand + streaming softor update (exp2 via exponent injection on
// the ALU pipe; only rcp touches MUFU). Mr init MUST be 0 (encoded values are
// ~1.26e9; Mr-Mn must not underflow int32).
#define ROW_UPD_I(vA, vB, vC, vD, Mr, Sr)                                          \
    {                                                                              \
        int m_  = min(min(vA, vB), min(vC, vD));                                   \
        int Mn  = max(Mr, m_);                                                     \
        float e0 = __int_as_float(min(max(Mn - (vA), -LIM), LIM) * 4096 + EB_LIT); \
        float e1 = __int_as_float(min(max(Mn - (vB), -LIM), LIM) * 4096 + EB_LIT); \
        float e2 = __int_as_float(min(max(Mn - (vC), -LIM), LIM) * 4096 + EB_LIT); \
        float e3 = __int_as_float(min(max(Mn - (vD), -LIM), LIM) * 4096 + EB_LIT); \
        float d_ = (e0 + e1) + (e2 + e3);                                          \
        float t_ = rcpf(d_);                                                       \
        float f_ = __int_as_float(max(Mr - Mn, -LIM) * 4096 + EB_ONE);             \
        Sr = fmaf(Sr, f_, t_);                                                     \
        Mr = Mn;                                                                   \
    }

// Kernel A: r_raw[c,b,g] = softor_S( softand_L( gather ) ), plus per-clause max.
// Rows live in shared as int4 log-domain encodings; one LDS.128 serves 4 rows.
// launch_bounds(256,3): 84 regs — room for the int temps AND software-pipelined
// LDS loads (the (256,4)=64-reg cap caused spills/serialized LDS in R5).
__global__ __launch_bounds__(256, 3) void clause_kernel(const float* __restrict__ x,
                                                        int step) {
    __shared__ int4 rows4[NG];   // 32 KB
    __shared__ float wmax[8];

    const int c  = blockIdx.z;
    const int b0 = blockIdx.y * 4;
    const int g0 = blockIdx.x * (NG / 4);
    const int tid = threadIdx.x;

    if (step == 0) {
        const float* __restrict__ xp = x + (size_t)b0 * NG;
        for (int i = tid; i < NG; i += 256) {
            int4 z;
            z.x = __float_as_int(fmaf(xp[i],          KF11, MAGF));
            z.y = __float_as_int(fmaf(xp[NG + i],     KF11, MAGF));
            z.z = __float_as_int(fmaf(xp[2 * NG + i], KF11, MAGF));
            z.w = __float_as_int(fmaf(xp[3 * NG + i], KF11, MAGF));
            rows4[i] = z;
        }
    } else {
        const float mg = fdec(d_mG[step - 1]);
        const float scK = ((mg > 1.0f) ? (1.0f / mg) : 1.0f) * KF11;
        const float* __restrict__ up = d_ubuf[(step - 1) & 1] + (size_t)(c * NB + b0) * NG;
        for (int i = tid; i < NG; i += 256) {
            int4 z;
            z.x = __float_as_int(fmaf(up[i],          scK, MAGF));
            z.y = __float_as_int(fmaf(up[NG + i],     scK, MAGF));
            z.z = __float_as_int(fmaf(up[2 * NG + i], scK, MAGF));
            z.w = __float_as_int(fmaf(up[3 * NG + i], scK, MAGF));
            rows4[i] = z;
        }
    }
    __syncthreads();

    float lmax = -1e30f;

    #pragma unroll
    for (int gg = 0; gg < 2; gg++) {
        const int g = g0 + gg * 256 + tid;
        const int lane = g & 31;
        const int4* __restrict__ ip = d_itr + ((size_t)(c * (NG/32) + (g >> 5)) * NS) * 32;

        int M0 = 0, M1 = 0, M2 = 0, M3 = 0;     // see encoding note above
        float S0 = 0.0f, S1 = 0.0f, S2 = 0.0f, S3 = 0.0f;

        int4 nxt = ip[lane];                       // s = 0, coalesced
        #pragma unroll
        for (int s = 0; s < NS; s++) {
            const int4 q = nxt;
            if (s < NS - 1) nxt = ip[(s + 1) * 32 + lane];
            const int4 A  = rows4[q.x];
            const int4 Bv = rows4[q.y];
            const int4 Cv = rows4[q.z];
            const int4 Dv = rows4[q.w];
            ROW_UPD_I(A.x, Bv.x, Cv.x, Dv.x, M0, S0);
            ROW_UPD_I(A.y, Bv.y, Cv.y, Dv.y, M1, S1);
            ROW_UPD_I(A.z, Bv.z, Cv.z, Dv.z, M2, S2);
            ROW_UPD_I(A.w, Bv.w, Cv.w, Dv.w, M3, S3);
        }

        // Decode running max back to value-domain: A = (Mr - MAGI)/KF11.
        const float r0 = fmaf(GLN2, lg2f(S0), (float)(M0 - MAGI) * (1.0f / KF11));
        const float r1 = fmaf(GLN2, lg2f(S1), (float)(M1 - MAGI) * (1.0f / KF11));
        const float r2 = fmaf(GLN2, lg2f(S2), (float)(M2 - MAGI) * (1.0f / KF11));
        const float r3 = fmaf(GLN2, lg2f(S3), (float)(M3 - MAGI) * (1.0f / KF11));

        float* __restrict__ rb = d_rbuf + (size_t)(c * NB + b0) * NG + g;
        rb[0]      = r0;
        rb[NG]     = r1;
        rb[2 * NG] = r2;
        rb[3 * NG] = r3;
        lmax = fmaxf(fmaxf(fmaxf(lmax, r0), fmaxf(r1, r2)), r3);
    }

    #pragma unroll
    for (int o = 16; o > 0; o >>= 1) lmax = fmaxf(lmax, __shfl_xor_sync(0xffffffffu, lmax, o));
    if ((tid & 31) == 0) wmax[tid >> 5] = lmax;
    __syncthreads();
    if (tid == 0) {
        float m2 = wmax[0];
        #pragma unroll
        for (int w = 1; w < 8; w++) m2 = fmaxf(m2, wmax[w]);
        atomicMax(&d_mC[step * NC + c], fenc(m2));
    }
}

// Kernel B: finalize r' with per-clause max, combine u = softor2(R, r'), track
// global max. 4 float4 per thread (MLP 8) — kernel is latency-bound.
__global__ __launch_bounds__(256) void combine_kernel(const float* __restrict__ x, int step) {
    __shared__ float wmax[8];
    const int tid = threadIdx.x;
    const int base = blockIdx.x * 4096;          // 4096-aligned => clause constant per block
    const int c = base >> 17;

    const float mc = fdec(d_mC[step * NC + c]);
    const float scC = (mc > 1.0f) ? (1.0f / mc) : 1.0f;

    float scP = 1.0f;
    if (step > 0) {
        const float mg = fdec(d_mG[step - 1]);
        if (mg > 1.0f) scP = 1.0f / mg;
    }

    const float4* __restrict__ rp = reinterpret_cast<const float4*>(d_rbuf + base);
    const float4* __restrict__ ap = (step == 0)
        ? reinterpret_cast<const float4*>(x + (base & (BG - 1)))
        : reinterpret_cast<const float4*>(d_ubuf[(step - 1) & 1] + base);
    float4* __restrict__ uo = reinterpret_cast<float4*>(d_ubuf[step & 1] + base);

    float lmax = -1e30f;
    #pragma unroll
    for (int k = 0; k < 4; k++) {
        const int i = k * 256 + tid;             // float4 index within block chunk
        const float4 rv = rp[i];
        const float4 av = ap[i];
        float4 u;
        {
            const float r = rv.x * scC, a = av.x * scP;
            const float M = fmaxf(a, r);
            u.x = fmaf(GLN2, lg2f(1.0f + ex2f(-fabsf(a - r) * KINV)), M);
        }
        {
            const float r = rv.y * scC, a = av.y * scP;
            const float M = fmaxf(a, r);
            u.y = fmaf(GLN2, lg2f(1.0f + ex2f(-fabsf(a - r) * KINV)), M);
        }
        {
            const float r = rv.z * scC, a = av.z * scP;
            const float M = fmaxf(a, r);
            u.z = fmaf(GLN2, lg2f(1.0f + ex2f(-fabsf(a - r) * KINV)), M);
        }
        {
            const float r = rv.w * scC, a = av.w * scP;
            const float M = fmaxf(a, r);
            u.w = fmaf(GLN2, lg2f(1.0f + ex2f(-fabsf(a - r) * KINV)), M);
        }
        uo[i] = u;
        lmax = fmaxf(fmaxf(fmaxf(lmax, u.x), fmaxf(u.y, u.z)), u.w);
    }

    #pragma unroll
    for (int o = 16; o > 0; o >>= 1) lmax = fmaxf(lmax, __shfl_xor_sync(0xffffffffu, lmax, o));
    if ((tid & 31) == 0) wmax[tid >> 5] = lmax;
    __syncthreads();
    if (tid == 0) {
        float m2 = wmax[0];
        #pragma unroll
        for (int w = 1; w < 8; w++) m2 = fmaxf(m2, wmax[w]);
        atomicMax(&d_mG[step], fenc(m2));
    }
}

__global__ __launch_bounds__(256) void final_kernel(float4* __restrict__ out) {
    const int i = blockIdx.x * 256 + threadIdx.x;
    const float mg = fdec(d_mG[NSTEPS - 1]);
    const float sc = (mg > 1.0f) ? (1.0f / mg) : 1.0f;
    const float4 v = reinterpret_cast<const float4*>(d_ubuf[(NSTEPS - 1) & 1])[i];
    out[i] = make_float4(v.x * sc, v.y * sc, v.z * sc, v.w * sc);
}

extern "C" void kernel_launch(void* const* d_in, const int* in_sizes, int n_in,
                              void* d_out, int out_size) {
    const float* x = (const float*)d_in[0];   // (B, G) float32
    const int*   I = (const int*)d_in[1];     // (C, G, S, L) int32

    init_max_kernel<<<1, 64>>>();
    transpose_I_kernel<<<(NC * NG * NS) / 256, 256>>>(I);

    dim3 gridA(4, NB / 4, NC);                // (g-quarter, b-group, clause)
    for (int t = 0; t < NSTEPS; t++) {
        clause_kernel<<<gridA, 256>>>(x, t);
        combine_kernel<<<TOT / 4096, 256>>>(x, t);
    }
    final_kernel<<<TOT / 1024, 256>>>((float4*)d_out);
}

// round 7
// speedup vs baseline: 1.5757x; 1.0597x over previous
#include <cuda_runtime.h>

// Problem constants: C=16, B=64, G=2048, S=8, L=4, infer_step=3.
#define NC 16
#define NB 64
#define NG 2048
#define NS 8
#define NL 4
#define NSTEPS 3
#define GAMMA 0.001f
#define KINV  1442.6950408889634f   /* 1000 * log2(e) */
#define GLN2  6.931471805599453e-4f /* gamma * ln(2)  */
#define BG (NB*NG)            // 131072 = 2^17
#define TOT (NC*NB*NG)        // 2097152

// u16 row quantization: q = round(v * QF), v in [0,1] -> q in [0, 61440].
#define QF    61440.0f
#define INVQ  (1.0f/61440.0f)
#define MAGF  12582912.0f           /* 1.5*2^23: fma(v,QF,MAGF) -> low mantissa = round(v*QF) */
// exp2(-(dq) * KINV/QF) via exponent injection: bits = EB - dq*KM.
#define KM    196976                /* round(KINV * 2^23 / QF) */
#define CLP   5365                  /* floor((126<<23)/KM): clamp so bits stay >= 0 */
#define CLP2  ((CLP) | ((CLP) << 16))
#define EB_LIT 1065056216           /* (127<<23) - 297000 (minimax bias, +-3.5%) */
#define EB_ONE 1065353216           /* (127<<23): exact 1.0 at dq==0 */

// Scratch (no cudaMalloc allowed).
__device__ float d_rbuf[TOT];
__device__ float d_ubuf[2][TOT];
__device__ int4  d_itr[NC * (NG/32) * NS * 32];   // transposed indices, 4MB
__device__ unsigned d_mC[NSTEPS * NC];
__device__ unsigned d_mG[NSTEPS];

__device__ __forceinline__ float ex2f(float x) { float y; asm("ex2.approx.f32 %0, %1;" : "=f"(y) : "f"(x)); return y; }
__device__ __forceinline__ float lg2f(float x) { float y; asm("lg2.approx.f32 %0, %1;" : "=f"(y) : "f"(x)); return y; }
__device__ __forceinline__ float rcpf(float x) { float y; asm("rcp.approx.f32 %0, %1;" : "=f"(y) : "f"(x)); return y; }
__device__ __forceinline__ unsigned minu2(unsigned a, unsigned b) {
    unsigned d; asm("min.u16x2 %0, %1, %2;" : "=r"(d) : "r"(a), "r"(b)); return d;
}
__device__ __forceinline__ unsigned maxu2(unsigned a, unsigned b) {
    unsigned d; asm("max.u16x2 %0, %1, %2;" : "=r"(d) : "r"(a), "r"(b)); return d;
}
__device__ __forceinline__ unsigned prmt(unsigned a, unsigned b, unsigned c) {
    unsigned d; asm("prmt.b32 %0, %1, %2, %3;" : "=r"(d) : "r"(a), "r"(b), "r"(c)); return d;
}

// Order-preserving float<->uint encoding so atomicMax works for any sign.
__device__ __forceinline__ unsigned fenc(float f) {
    unsigned u = __float_as_uint(f);
    return (u & 0x80000000u) ? ~u : (u | 0x80000000u);
}
__device__ __forceinline__ float fdec(unsigned u) {
    return __uint_as_float((u & 0x80000000u) ? (u ^ 0x80000000u) : ~u);
}

__global__ void init_max_kernel() {
    int t = threadIdx.x;
    if (t < NSTEPS * NC) d_mC[t] = 0u;
    if (t < NSTEPS)      d_mG[t] = 0u;
}

// One-time transpose of I for coalesced hot-loop index loads.
__global__ __launch_bounds__(256) void transpose_I_kernel(const int* __restrict__ I) {
    const int t  = blockIdx.x * 256 + threadIdx.x;
    const int gl = t & 31;
    const int s  = (t >> 5) & 7;
    const int gb = (t >> 8) & 63;
    const int c  = t >> 14;
    const int4* __restrict__ in = reinterpret_cast<const int4*>(I);
    d_itr[t] = in[((size_t)(c * NG + gb * 32 + gl)) * NS + s];
}

// Packed-pair softand + streaming-softor update for rows (2j, 2j+1).
// All diffs are half-wise non-negative (against packed min / old packed max),
// so plain 32-bit subtraction is an exact u16x2 SIMD sub.
// term_s = exp((m-Mn)/g) / sum_l exp((m-v_l)/g); rescale by exp((Mr_old-Mn)/g).
#define PAIR_UPD(La, Lb, Lc, Ld, Mr, Slo, Shi)                                     \
    {                                                                              \
        unsigned pm = minu2(minu2(La, Lb), minu2(Lc, Ld));                         \
        unsigned Mn = maxu2(Mr, pm);                                               \
        unsigned q0 = minu2((La) - pm, CLP2);                                      \
        unsigned q1 = minu2((Lb) - pm, CLP2);                                      \
        unsigned q2 = minu2((Lc) - pm, CLP2);                                      \
        unsigned q3 = minu2((Ld) - pm, CLP2);                                      \
        float e0l = __int_as_float(EB_LIT - (int)(q0 & 0xFFFFu) * KM);             \
        float e1l = __int_as_float(EB_LIT - (int)(q1 & 0xFFFFu) * KM);             \
        float e2l = __int_as_float(EB_LIT - (int)(q2 & 0xFFFFu) * KM);             \
        float e3l = __int_as_float(EB_LIT - (int)(q3 & 0xFFFFu) * KM);             \
        float e0h = __int_as_float(EB_LIT - (int)(q0 >> 16) * KM);                 \
        float e1h = __int_as_float(EB_LIT - (int)(q1 >> 16) * KM);                 \
        float e2h = __int_as_float(EB_LIT - (int)(q2 >> 16) * KM);                 \
        float e3h = __int_as_float(EB_LIT - (int)(q3 >> 16) * KM);                 \
        float tl = rcpf((e0l + e1l) + (e2l + e3l));                                \
        float th = rcpf((e0h + e1h) + (e2h + e3h));                                \
        unsigned dm = minu2(Mn - pm, CLP2);                                        \
        unsigned dr = minu2(Mn - (Mr), CLP2);                                      \
        float fml = __int_as_float(EB_ONE - (int)(dm & 0xFFFFu) * KM);             \
        float fmh = __int_as_float(EB_ONE - (int)(dm >> 16) * KM);                 \
        float frl = __int_as_float(EB_ONE - (int)(dr & 0xFFFFu) * KM);             \
        float frh = __int_as_float(EB_ONE - (int)(dr >> 16) * KM);                 \
        Slo = fmaf(Slo, frl, fml * tl);                                            \
        Shi = fmaf(Shi, frh, fmh * th);                                            \
        Mr = Mn;                                                                   \
    }

// Kernel A: r_raw[c,b,g] = softor_S( softand_L( gather ) ), plus per-clause max.
// 8 batch rows packed as u16 pairs in uint4; one LDS.128 serves all 8 rows.
__global__ __launch_bounds__(256, 3) void clause_kernel(const float* __restrict__ x,
                                                        int step) {
    __shared__ uint4 rows8[NG];   // 32 KB: 8 rows x u16 per gather index
    __shared__ float wmax[8];

    const int c  = blockIdx.z;
    const int b0 = blockIdx.y * 8;
    const int g0 = blockIdx.x * 256;
    const int tid = threadIdx.x;

    // Fill: quantize 8 rows to u16, pack pairs via float-magic + PRMT.
    {
        float sc = QF;
        const float* __restrict__ vp;
        if (step == 0) {
            vp = x + (size_t)b0 * NG;
        } else {
            const float mg = fdec(d_mG[step - 1]);
            sc = ((mg > 1.0f) ? (1.0f / mg) : 1.0f) * QF;
            vp = d_ubuf[(step - 1) & 1] + (size_t)(c * NB + b0) * NG;
        }
        for (int i = tid; i < NG; i += 256) {
            uint4 z;
            #pragma unroll
            for (int j = 0; j < 4; j++) {
                unsigned a = __float_as_uint(fmaf(vp[(2 * j) * NG + i],     sc, MAGF));
                unsigned b = __float_as_uint(fmaf(vp[(2 * j + 1) * NG + i], sc, MAGF));
                (&z.x)[j] = prmt(a, b, 0x5410u);   // lo16(a) | lo16(b)<<16
            }
            rows8[i] = z;
        }
    }
    __syncthreads();

    const int g = g0 + tid;
    const int lane = g & 31;
    const int4* __restrict__ ip = d_itr + ((size_t)(c * (NG/32) + (g >> 5)) * NS) * 32;

    uint4 Mr = make_uint4(0u, 0u, 0u, 0u);
    float S0 = 0.f, S1 = 0.f, S2 = 0.f, S3 = 0.f, S4 = 0.f, S5 = 0.f, S6 = 0.f, S7 = 0.f;

    int4 nxt = ip[lane];                       // s = 0, coalesced
    #pragma unroll
    for (int s = 0; s < NS; s++) {
        const int4 q = nxt;
        if (s < NS - 1) nxt = ip[(s + 1) * 32 + lane];
        const uint4 A  = rows8[q.x];
        const uint4 Bv = rows8[q.y];
        const uint4 Cv = rows8[q.z];
        const uint4 Dv = rows8[q.w];
        PAIR_UPD(A.x, Bv.x, Cv.x, Dv.x, Mr.x, S0, S1);
        PAIR_UPD(A.y, Bv.y, Cv.y, Dv.y, Mr.y, S2, S3);
        PAIR_UPD(A.z, Bv.z, Cv.z, Dv.z, Mr.z, S4, S5);
        PAIR_UPD(A.w, Bv.w, Cv.w, Dv.w, Mr.w, S6, S7);
    }

    // Decode: r = Mn/Q + gamma*ln(S).
    float* __restrict__ rb = d_rbuf + (size_t)(c * NB + b0) * NG + g;
    float lmax = -1e30f;
    {
        const float r0 = fmaf(GLN2, lg2f(S0), (float)(Mr.x & 0xFFFFu) * INVQ);
        const float r1 = fmaf(GLN2, lg2f(S1), (float)(Mr.x >> 16)     * INVQ);
        const float r2 = fmaf(GLN2, lg2f(S2), (float)(Mr.y & 0xFFFFu) * INVQ);
        const float r3 = fmaf(GLN2, lg2f(S3), (float)(Mr.y >> 16)     * INVQ);
        const float r4 = fmaf(GLN2, lg2f(S4), (float)(Mr.z & 0xFFFFu) * INVQ);
        const float r5 = fmaf(GLN2, lg2f(S5), (float)(Mr.z >> 16)     * INVQ);
        const float r6 = fmaf(GLN2, lg2f(S6), (float)(Mr.w & 0xFFFFu) * INVQ);
        const float r7 = fmaf(GLN2, lg2f(S7), (float)(Mr.w >> 16)     * INVQ);
        rb[0]      = r0;  rb[NG]     = r1;
        rb[2 * NG] = r2;  rb[3 * NG] = r3;
        rb[4 * NG] = r4;  rb[5 * NG] = r5;
        rb[6 * NG] = r6;  rb[7 * NG] = r7;
        lmax = fmaxf(fmaxf(fmaxf(r0, r1), fmaxf(r2, r3)),
                     fmaxf(fmaxf(r4, r5), fmaxf(r6, r7)));
    }

    #pragma unroll
    for (int o = 16; o > 0; o >>= 1) lmax = fmaxf(lmax, __shfl_xor_sync(0xffffffffu, lmax, o));
    if ((tid & 31) == 0) wmax[tid >> 5] = lmax;
    __syncthreads();
    if (tid == 0) {
        float m2 = wmax[0];
        #pragma unroll
        for (int w = 1; w < 8; w++) m2 = fmaxf(m2, wmax[w]);
        atomicMax(&d_mC[step * NC + c], fenc(m2));
    }
}

// Kernel B: finalize r', combine u = softor2(R, r'), track global max.
// 1 float4/thread, grid 2048 — kernel was grid-starved/latency-bound.
__global__ __launch_bounds__(256) void combine_kernel(const float* __restrict__ x, int step) {
    __shared__ float wmax[8];
    const int tid = threadIdx.x;
    const int base = blockIdx.x * 1024;          // 1024-aligned => clause constant per block
    const int c = base >> 17;

    const float mc = fdec(d_mC[step * NC + c]);
    const float scC = (mc > 1.0f) ? (1.0f / mc) : 1.0f;

    float scP = 1.0f;
    if (step > 0) {
        const float mg = fdec(d_mG[step - 1]);
        if (mg > 1.0f) scP = 1.0f / mg;
    }

    const float4 rv = reinterpret_cast<const float4*>(d_rbuf + base)[tid];
    const float4 av = (step == 0)
        ? reinterpret_cast<const float4*>(x + (base & (BG - 1)))[tid]
        : reinterpret_cast<const float4*>(d_ubuf[(step - 1) & 1] + base)[tid];

    float4 u;
    {
        const float r = rv.x * scC, a = av.x * scP;
        const float M = fmaxf(a, r);
        u.x = fmaf(GLN2, lg2f(1.0f + ex2f(-fabsf(a - r) * KINV)), M);
    }
    {
        const float r = rv.y * scC, a = av.y * scP;
        const float M = fmaxf(a, r);
        u.y = fmaf(GLN2, lg2f(1.0f + ex2f(-fabsf(a - r) * KINV)), M);
    }
    {
        const float r = rv.z * scC, a = av.z * scP;
        const float M = fmaxf(a, r);
        u.z = fmaf(GLN2, lg2f(1.0f + ex2f(-fabsf(a - r) * KINV)), M);
    }
    {
        const float r = rv.w * scC, a = av.w * scP;
        const float M = fmaxf(a, r);
        u.w = fmaf(GLN2, lg2f(1.0f + ex2f(-fabsf(a - r) * KINV)), M);
    }
    reinterpret_cast<float4*>(d_ubuf[step & 1] + base)[tid] = u;
    float lmax = fmaxf(fmaxf(u.x, u.y), fmaxf(u.z, u.w));

    #pragma unroll
    for (int o = 16; o > 0; o >>= 1) lmax = fmaxf(lmax, __shfl_xor_sync(0xffffffffu, lmax, o));
    if ((tid & 31) == 0) wmax[tid >> 5] = lmax;
    __syncthreads();
    if (tid == 0) {
        float m2 = wmax[0];
        #pragma unroll
        for (int w = 1; w < 8; w++) m2 = fmaxf(m2, wmax[w]);
        atomicMax(&d_mG[step], fenc(m2));
    }
}

__global__ __launch_bounds__(256) void final_kernel(float4* __restrict__ out) {
    const int i = blockIdx.x * 256 + threadIdx.x;
    const float mg = fdec(d_mG[NSTEPS - 1]);
    const float sc = (mg > 1.0f) ? (1.0f / mg) : 1.0f;
    const float4 v = reinterpret_cast<const float4*>(d_ubuf[(NSTEPS - 1) & 1])[i];
    out[i] = make_float4(v.x * sc, v.y * sc, v.z * sc, v.w * sc);
}

extern "C" void kernel_launch(void* const* d_in, const int* in_sizes, int n_in,
                              void* d_out, int out_size) {
    const float* x = (const float*)d_in[0];   // (B, G) float32
    const int*   I = (const int*)d_in[1];     // (C, G, S, L) int32

    init_max_kernel<<<1, 64>>>();
    transpose_I_kernel<<<(NC * NG * NS) / 256, 256>>>(I);

    dim3 gridA(NG / 256, NB / 8, NC);         // (8, 8, 16) = 1024 blocks
    for (int t = 0; t < NSTEPS; t++) {
        clause_kernel<<<gridA, 256>>>(x, t);
        combine_kernel<<<TOT / 1024, 256>>>(x, t);
    }
    final_kernel<<<TOT / 1024, 256>>>((float4*)d_out);
}